// round 8
// baseline (speedup 1.0000x reference)
#include <cuda_runtime.h>
#include <cuda_fp16.h>
#include <math.h>
#include <stdint.h>

#define BB 2
#define SS 2048
#define DD 1024
#define HH 16
#define HD 64
#define CC 16
#define BS (BB*SS)
#define BH (BB*HH)

// ---------------- device scratch ----------------
__device__ __align__(256) float  g_xn[BS*DD];
__device__ __align__(256) __half g_xnh[BS*DD];
__device__ __align__(256) __half g_qh[BH*SS*HD];
__device__ __align__(256) __half g_kh[BH*SS*HD];
__device__ __align__(256) __half g_vh[BH*SS*HD];
__device__ __align__(256) __half g_atth[BS*DD];
__device__ __align__(256) float  g_proj[BS*DD];
__device__ __align__(256) __half g_wqkvh[3*DD*DD];
__device__ __align__(256) __half g_wouth[DD*DD];
__device__ __align__(256) float  g_l[BH*SS];
__device__ __align__(256) __half g_wh[(size_t)BH*SS*SS];   // unnormalized exp(S), fp16
__device__ __align__(256) float  g_w[(size_t)BH*SS*SS];    // fallback w buffer

__device__ float c_h1[DD];
__device__ float c_cepre[DD];
__device__ float c_gate_a[HH];
__device__ float c_gate_v[HH];
__device__ float c_misc[2];
__device__ float c_alpha[HH];
__device__ float c_beta[HH];
__device__ float c_vadd[DD];

// ---------------- helpers ----------------
__device__ __forceinline__ uint32_t pack_h2(float a, float b) {
    __half2 h = __floats2half2_rn(a, b);
    return *reinterpret_cast<uint32_t*>(&h);
}

__device__ __forceinline__ float fast_exp2(float x) {
    float z = x + 12582912.0f;
    int   i = __float_as_int(z);
    float f = x - (z - 12582912.0f);
    float p = 9.618129e-3f;
    p = fmaf(p, f, 5.5504109e-2f);
    p = fmaf(p, f, 2.4022651e-1f);
    p = fmaf(p, f, 6.9314718e-1f);
    p = fmaf(p, f, 1.0f);
    return __int_as_float(__float_as_int(p) + (i << 23));
}

__device__ __forceinline__ void mma_f16(float c[4], const uint32_t a[4],
                                        uint32_t b0, uint32_t b1) {
    asm volatile(
        "mma.sync.aligned.m16n8k16.row.col.f32.f16.f16.f32 "
        "{%0,%1,%2,%3}, {%4,%5,%6,%7}, {%8,%9}, {%0,%1,%2,%3};"
        : "+f"(c[0]), "+f"(c[1]), "+f"(c[2]), "+f"(c[3])
        : "r"(a[0]), "r"(a[1]), "r"(a[2]), "r"(a[3]), "r"(b0), "r"(b1));
}

__device__ __forceinline__ uint32_t lds_addr(const void* p) {
    return (uint32_t)__cvta_generic_to_shared(p);
}
__device__ __forceinline__ void ldsm4(uint32_t r[4], uint32_t a) {
    asm volatile("ldmatrix.sync.aligned.m8n8.x4.shared.b16 {%0,%1,%2,%3}, [%4];"
                 : "=r"(r[0]), "=r"(r[1]), "=r"(r[2]), "=r"(r[3]) : "r"(a));
}
__device__ __forceinline__ void ldsm4t(uint32_t r[4], uint32_t a) {
    asm volatile("ldmatrix.sync.aligned.m8n8.x4.trans.shared.b16 {%0,%1,%2,%3}, [%4];"
                 : "=r"(r[0]), "=r"(r[1]), "=r"(r[2]), "=r"(r[3]) : "r"(a));
}

__device__ __forceinline__ void cp16h(__half* dst, const __half* src) {
    unsigned d = (unsigned)__cvta_generic_to_shared(dst);
    asm volatile("cp.async.cg.shared.global [%0], [%1], 16;" :: "r"(d), "l"(src));
}
__device__ __forceinline__ void cp_commit() { asm volatile("cp.async.commit_group;"); }
__device__ __forceinline__ void cp_wait1() { asm volatile("cp.async.wait_group 1;"); }
__device__ __forceinline__ void cp_wait0() { asm volatile("cp.async.wait_group 0;"); }

__device__ __forceinline__ void st_cs_u32(__half* p, uint32_t v) {
    asm volatile("st.global.cs.b32 [%0], %1;" :: "l"(p), "r"(v));
}

// ---------------- chaos encoder ----------------
__global__ void chaos1_kernel(const float* __restrict__ cf,
                              const float* __restrict__ W1, const float* __restrict__ b1,
                              const float* __restrict__ g1, const float* __restrict__ bb1,
                              const float* __restrict__ Wga, const float* __restrict__ bga,
                              const float* __restrict__ Wgv, const float* __restrict__ bgv,
                              const float* __restrict__ Wt,  const float* __restrict__ bt) {
    __shared__ float cfs[CC];
    __shared__ float red[256], red2[256];
    int t = threadIdx.x;
    if (t < CC) cfs[t] = cf[t];
    __syncthreads();

    if (t < HH) {
        float sa = bga[t], sv = bgv[t];
        #pragma unroll
        for (int c = 0; c < CC; c++) { sa += cfs[c]*Wga[t*CC+c]; sv += cfs[c]*Wgv[t*CC+c]; }
        c_gate_a[t] = 1.f/(1.f+expf(-sa));
        c_gate_v[t] = 1.f/(1.f+expf(-sv));
    } else if (t == 16) {
        float s = bt[0];
        #pragma unroll
        for (int c = 0; c < CC; c++) s += cfs[c]*Wt[c];
        float sp = (s > 20.f) ? s : log1pf(expf(s));
        c_misc[0] = sp + 1.0f;
    } else if (t == 17) {
        float s = 0.f;
        #pragma unroll
        for (int c = 0; c < CC; c++) s += cfs[c];
        s *= (1.0f/CC);
        c_misc[1] = (1.f/(1.f+expf(-s)))*0.5f + 0.5f;
    }

    float vals[4];
    float s1 = 0.f, s2 = 0.f;
    #pragma unroll
    for (int l = 0; l < 4; l++) {
        int i = t*4 + l;
        float a = b1[i];
        #pragma unroll
        for (int c = 0; c < CC; c++) a += cfs[c]*W1[i*CC+c];
        vals[l] = a; s1 += a; s2 += a*a;
    }
    red[t] = s1; red2[t] = s2; __syncthreads();
    for (int o = 128; o > 0; o >>= 1) {
        if (t < o) { red[t] += red[t+o]; red2[t] += red2[t+o]; }
        __syncthreads();
    }
    float m = red[0]*(1.0f/DD);
    float var = red2[0]*(1.0f/DD) - m*m;
    float inv = rsqrtf(var + 1e-5f);
    #pragma unroll
    for (int l = 0; l < 4; l++) {
        int i = t*4 + l;
        float h = (vals[l]-m)*inv*g1[i] + bb1[i];
        c_h1[i] = fmaxf(h, 0.f);
    }
}

__global__ void chaos2_kernel(const float* __restrict__ W2, const float* __restrict__ b2) {
    __shared__ float h1s[DD];
    __shared__ float red[256];
    int t = threadIdx.x;
    #pragma unroll
    for (int l = 0; l < 4; l++) h1s[t + l*256] = c_h1[t + l*256];
    __syncthreads();
    int r = t >> 4, c = t & 15;
    int i = blockIdx.x*16 + r;
    float s = 0.f;
    for (int j = c; j < DD; j += 16) s += h1s[j]*W2[(size_t)i*DD + j];
    red[t] = s; __syncthreads();
    for (int o = 8; o > 0; o >>= 1) {
        if (c < o) red[t] += red[t+o];
        __syncthreads();
    }
    if (c == 0) c_cepre[i] = red[r*16] + b2[i];
}

__global__ void chaos3_kernel(const float* __restrict__ g2, const float* __restrict__ bb2,
                              const float* __restrict__ qrot, const float* __restrict__ fscales) {
    __shared__ float ce[DD];
    __shared__ float scs[DD];
    __shared__ float red[256], red2[256];
    int t = threadIdx.x;
    float vals[4]; float s1 = 0.f, s2 = 0.f;
    #pragma unroll
    for (int l = 0; l < 4; l++) {
        int i = t + l*256;
        vals[l] = c_cepre[i]; s1 += vals[l]; s2 += vals[l]*vals[l];
    }
    red[t] = s1; red2[t] = s2; __syncthreads();
    for (int o = 128; o > 0; o >>= 1) {
        if (t < o) { red[t] += red[t+o]; red2[t] += red2[t+o]; }
        __syncthreads();
    }
    float m = red[0]*(1.0f/DD);
    float var = red2[0]*(1.0f/DD) - m*m;
    float inv = rsqrtf(var + 1e-5f);
    #pragma unroll
    for (int l = 0; l < 4; l++) {
        int i = t + l*256;
        ce[i] = (vals[l]-m)*inv*g2[i] + bb2[i];
    }
    __syncthreads();
    float sfs = 1.f/(1.f+expf(-fscales[0]));
    #pragma unroll
    for (int l = 0; l < 4; l++) {
        int i = t + l*256;
        int h = i >> 6, d = i & 63;
        float s = 0.f;
        #pragma unroll 8
        for (int e = 0; e < HD; e++) s += ce[h*HD+e]*qrot[e*HD+d];
        s *= sfs;
        scs[i] = s;
        c_vadd[i] = s * c_gate_v[h];
    }
    __syncthreads();
    if (t < HH) {
        float bsum = 0.f;
        for (int d = 0; d < HD; d++) bsum += scs[t*HD + d];
        float temp = c_misc[0];
        c_alpha[t] = c_gate_a[t]/(8.f*temp);
        c_beta[t]  = bsum/temp;
    }
}

// ---------------- LN-pre ----------------
__global__ void ln_pre_kernel(const float* __restrict__ x,
                              const float* __restrict__ g, const float* __restrict__ b) {
    __shared__ float red[256], red2[256];
    size_t row = blockIdx.x;
    const float4* xr = (const float4*)(x + row*DD);
    int t = threadIdx.x;
    float4 v = xr[t];
    float s1 = v.x + v.y + v.z + v.w;
    float s2 = v.x*v.x + v.y*v.y + v.z*v.z + v.w*v.w;
    red[t] = s1; red2[t] = s2; __syncthreads();
    for (int off = 128; off > 0; off >>= 1) {
        if (t < off) { red[t] += red[t+off]; red2[t] += red2[t+off]; }
        __syncthreads();
    }
    float m = red[0]*(1.0f/DD);
    float var = red2[0]*(1.0f/DD) - m*m;
    float inv = rsqrtf(var + 1e-5f);
    int i = t*4;
    float4 gg = *(const float4*)(g + i);
    float4 bb = *(const float4*)(b + i);
    float4 o;
    o.x = (v.x-m)*inv*gg.x + bb.x;
    o.y = (v.y-m)*inv*gg.y + bb.y;
    o.z = (v.z-m)*inv*gg.z + bb.z;
    o.w = (v.w-m)*inv*gg.w + bb.w;
    *(float4*)(g_xn + row*DD + i) = o;
    uint2 h;
    h.x = pack_h2(o.x, o.y);
    h.y = pack_h2(o.z, o.w);
    *(uint2*)(g_xnh + row*DD + i) = h;
}

// ---------------- convert weights to half ----------------
__global__ void round_weights(const float* __restrict__ Wqkv,
                              const float* __restrict__ Wout) {
    size_t i = (size_t)blockIdx.x*256 + threadIdx.x;
    const size_t nqkv = (size_t)3*DD*DD/4;
    float4 v;
    __half* dst;
    if (i < nqkv) {
        v = ((const float4*)Wqkv)[i];
        dst = g_wqkvh + i*4;
    } else {
        v = ((const float4*)Wout)[i - nqkv];
        dst = g_wouth + (i - nqkv)*4;
    }
    uint2 h;
    h.x = pack_h2(v.x, v.y);
    h.y = pack_h2(v.z, v.w);
    *(uint2*)dst = h;
}

// ============================================================================
// fp16 tensor-core GEMM (NT) with ldmatrix fragment loads.
// ============================================================================
#define GE_BK 64
#define GE_STR 72
#define GE_TILE_H (128*GE_STR)
#define GE_SMEM_BYTES (4*GE_TILE_H*2)

struct EpiQKV {
    const float* bias;
    __device__ __forceinline__ void write2(int m, int n, float v0, float v1) const {
        v0 += bias[n]; v1 += bias[n+1];
        int b = m >> 11, s = m & 2047;
        int which = n >> 10, rest = n & 1023;
        int h = rest >> 6, dd = rest & 63;
        int bh = b*HH + h;
        size_t dst = ((size_t)bh*SS + s)*HD + dd;
        if (which == 0) {
            *(uint32_t*)&g_qh[dst] = pack_h2(v0, v1);
        } else if (which == 1) {
            *(uint32_t*)&g_kh[dst] = pack_h2(v0, v1);
        } else {
            v0 += c_vadd[rest]; v1 += c_vadd[rest+1];
            *(uint32_t*)&g_vh[dst] = pack_h2(v0, v1);
        }
    }
};

struct EpiOut {
    const float* bias;
    __device__ __forceinline__ void write2(int m, int n, float v0, float v1) const {
        float2 o = make_float2(v0 + bias[n], v1 + bias[n+1]);
        *(float2*)&g_proj[(size_t)m*DD + n] = o;
    }
};

__device__ __forceinline__ void ge_load(__half* dstA, __half* dstB,
                                        const __half* A, const __half* B,
                                        int m0, int n0, int k0, int t) {
    #pragma unroll
    for (int i = 0; i < 4; i++) {
        int f = t + i*256;
        int row = f >> 3, c = f & 7;
        cp16h(dstA + row*GE_STR + c*8, A + (size_t)(m0+row)*DD + k0 + c*8);
    }
    #pragma unroll
    for (int i = 0; i < 4; i++) {
        int f = t + i*256;
        int row = f >> 3, c = f & 7;
        cp16h(dstB + row*GE_STR + c*8, B + (size_t)(n0+row)*DD + k0 + c*8);
    }
}

template<typename Epi>
__global__ void __launch_bounds__(256) gemm_f16(
    const __half* __restrict__ A, const __half* __restrict__ B, Epi epi)
{
    extern __shared__ __half gsm[];
    __half* As[2] = { gsm,                gsm + 2*GE_TILE_H };
    __half* Bs[2] = { gsm + GE_TILE_H,    gsm + 3*GE_TILE_H };

    int t = threadIdx.x, lane = t & 31, warp = t >> 5;
    int q = lane >> 2, r = lane & 3;
    int wm = (warp >> 1) * 32;
    int wn = (warp & 1) * 64;
    int m0 = blockIdx.y * 128, n0 = blockIdx.x * 128;

    int a_off = (wm + (lane & 15))*GE_STR + (lane >> 4)*8;
    int b_off = (wn + (lane & 7) + ((lane & 16) >> 1))*GE_STR + (lane & 8);

    float acc[2][8][4] = {};

    ge_load(As[0], Bs[0], A, B, m0, n0, 0, t);
    cp_commit();

    for (int kt = 0; kt < DD/GE_BK; kt++) {
        int cur = kt & 1;
        if (kt + 1 < DD/GE_BK) {
            ge_load(As[cur^1], Bs[cur^1], A, B, m0, n0, (kt+1)*GE_BK, t);
            cp_commit();
            cp_wait1();
        } else {
            cp_wait0();
        }
        __syncthreads();

        uint32_t asb = lds_addr(As[cur]);
        uint32_t bsb = lds_addr(Bs[cur]);
        #pragma unroll
        for (int ks = 0; ks < 4; ks++) {
            uint32_t af[2][4];
            ldsm4(af[0], asb + 2*(a_off + ks*16));
            ldsm4(af[1], asb + 2*(a_off + 16*GE_STR + ks*16));
            #pragma unroll
            for (int p = 0; p < 4; p++) {
                uint32_t bb[4];
                ldsm4(bb, bsb + 2*(b_off + p*16*GE_STR + ks*16));
                mma_f16(acc[0][2*p],   af[0], bb[0], bb[1]);
                mma_f16(acc[0][2*p+1], af[0], bb[2], bb[3]);
                mma_f16(acc[1][2*p],   af[1], bb[0], bb[1]);
                mma_f16(acc[1][2*p+1], af[1], bb[2], bb[3]);
            }
        }
        __syncthreads();
    }

    #pragma unroll
    for (int mi = 0; mi < 2; mi++)
        #pragma unroll
        for (int nj = 0; nj < 8; nj++) {
            int m = m0 + wm + mi*16 + q;
            int n = n0 + wn + nj*8 + 2*r;
            epi.write2(m,     n, acc[mi][nj][0], acc[mi][nj][1]);
            epi.write2(m + 8, n, acc[mi][nj][2], acc[mi][nj][3]);
        }
}

// ============================================================================
// Attention pass 1 (bh-half): S=QK^T -> exp2 -> rowsum + O += P@V.
// Writes unnormalized exp(S) (fp16, the SAME packed values PV consumes)
// to g_wh, plus row sums to g_l.  No second pass over K.
// ============================================================================
#define QS_STR 72
#define Q_HALVES (128*QS_STR)
#define ATT_SMEM_BYTES (5*Q_HALVES*2)   // Q,K0,K1,V0,V1 = 92160

__device__ __forceinline__ void att_load_k(__half* dst, const __half* src, int t) {
    #pragma unroll
    for (int i = 0; i < 4; i++) {
        int f = t + i*256;
        int row = f >> 3, c = f & 7;
        cp16h(dst + row*QS_STR + c*8, src + (size_t)row*HD + c*8);
    }
}

__global__ void __launch_bounds__(256, 1) attn_pass1(
    const __half* __restrict__ qg, const __half* __restrict__ kg,
    const __half* __restrict__ vg, int bh0)
{
    extern __shared__ __half asm_[];
    __half* qs  = asm_;
    __half* ks0 = asm_ + Q_HALVES;
    __half* ks1 = asm_ + 2*Q_HALVES;
    __half* vs0 = asm_ + 3*Q_HALVES;
    __half* vs1 = asm_ + 4*Q_HALVES;
    __shared__ float l_part[2][128];

    int t = threadIdx.x, lane = t & 31, warp = t >> 5;
    int q = lane >> 2, r = lane & 3;
    int wr = warp >> 1, wc = warp & 1;
    int m0 = blockIdx.x*128, bh = bh0 + blockIdx.y;
    int h = bh & 15, b = bh >> 4;
    const __half* Q = qg + ((size_t)bh*SS + m0)*HD;
    const __half* K = kg + (size_t)bh*SS*HD;
    const __half* V = vg + (size_t)bh*SS*HD;
    const float LOG2E = 1.4426950408889634f;
    float al2 = c_alpha[h]*LOG2E, be2 = c_beta[h]*LOG2E;

    // w store base for this warp's rows
    __half* whb = g_wh + (size_t)bh*SS*SS + (size_t)(m0 + wr*32)*SS;

    #pragma unroll
    for (int i = 0; i < 4; i++) {
        int f = t + i*256;
        int row = f >> 3, c = f & 7;
        *(uint4*)&qs[row*QS_STR + c*8] = *(const uint4*)(Q + (size_t)row*HD + c*8);
    }

    att_load_k(ks0, K, t);
    att_load_k(vs0, V, t);
    cp_commit();
    __syncthreads();

    uint32_t qf[2][4][4];
    {
        uint32_t qsb = lds_addr(qs);
        int q_off = (wr*32 + (lane & 15))*QS_STR + (lane >> 4)*8;
        #pragma unroll
        for (int mi = 0; mi < 2; mi++)
            #pragma unroll
            for (int ks = 0; ks < 4; ks++)
                ldsm4(qf[mi][ks], qsb + 2*(q_off + mi*16*QS_STR + ks*16));
    }

    int k_off = (wc*64 + (lane & 7) + ((lane & 16) >> 1))*QS_STR + (lane & 8);
    int v_off = (wc*64 + (lane & 15))*QS_STR + (lane >> 4)*8;

    float O[2][8][4] = {};
    float rs[2][2] = {};

    for (int kt = 0; kt < 16; kt++) {
        __half* kss = (kt & 1) ? ks1 : ks0;
        __half* vss = (kt & 1) ? vs1 : vs0;
        if (kt < 15) {
            att_load_k((kt & 1) ? ks0 : ks1, K + (size_t)(kt+1)*128*HD, t);
            att_load_k((kt & 1) ? vs0 : vs1, V + (size_t)(kt+1)*128*HD, t);
            cp_commit();
            cp_wait1();
        } else {
            cp_wait0();
        }
        __syncthreads();

        // ---- S = Q K^T ----
        float acc[2][8][4] = {};
        uint32_t ksb = lds_addr(kss);
        #pragma unroll
        for (int ks = 0; ks < 4; ks++) {
            #pragma unroll
            for (int p = 0; p < 4; p++) {
                uint32_t bb[4];
                ldsm4(bb, ksb + 2*(k_off + p*16*QS_STR + ks*16));
                mma_f16(acc[0][2*p],   qf[0][ks], bb[0], bb[1]);
                mma_f16(acc[0][2*p+1], qf[0][ks], bb[2], bb[3]);
                mma_f16(acc[1][2*p],   qf[1][ks], bb[0], bb[1]);
                mma_f16(acc[1][2*p+1], qf[1][ks], bb[2], bb[3]);
            }
        }
        // ---- exp + rowsum ----
        #pragma unroll
        for (int mi = 0; mi < 2; mi++)
            #pragma unroll
            for (int nj = 0; nj < 8; nj++) {
                float e0 = fast_exp2(fmaf(al2, acc[mi][nj][0], be2));
                float e1 = fast_exp2(fmaf(al2, acc[mi][nj][1], be2));
                float e2 = fast_exp2(fmaf(al2, acc[mi][nj][2], be2));
                float e3 = fast_exp2(fmaf(al2, acc[mi][nj][3], be2));
                acc[mi][nj][0] = e0; acc[mi][nj][1] = e1;
                acc[mi][nj][2] = e2; acc[mi][nj][3] = e3;
                rs[mi][0] += e0 + e1;
                rs[mi][1] += e2 + e3;
            }
        // ---- O += P @ V + stream unnormalized w (same packed values) ----
        uint32_t vsb = lds_addr(vss);
        #pragma unroll
        for (int kk = 0; kk < 4; kk++) {
            uint32_t af[2][4];
            #pragma unroll
            for (int mi = 0; mi < 2; mi++) {
                af[mi][0] = pack_h2(acc[mi][2*kk][0],   acc[mi][2*kk][1]);
                af[mi][1] = pack_h2(acc[mi][2*kk][2],   acc[mi][2*kk][3]);
                af[mi][2] = pack_h2(acc[mi][2*kk+1][0], acc[mi][2*kk+1][1]);
                af[mi][3] = pack_h2(acc[mi][2*kk+1][2], acc[mi][2*kk+1][3]);
                // store w (unnormalized): rows (mi*16+q, +8), cols kk*16+2r (+8)
                size_t rb = (size_t)(mi*16 + q)*SS + kt*128 + wc*64 + kk*16 + 2*r;
                st_cs_u32(whb + rb,            af[mi][0]);
                st_cs_u32(whb + rb + 8*SS,     af[mi][1]);
                st_cs_u32(whb + rb + 8,        af[mi][2]);
                st_cs_u32(whb + rb + 8*SS + 8, af[mi][3]);
            }
            #pragma unroll
            for (int p = 0; p < 4; p++) {
                uint32_t bb[4];
                ldsm4t(bb, vsb + 2*(v_off + kk*16*QS_STR + p*16));
                mma_f16(O[0][2*p],   af[0], bb[0], bb[1]);
                mma_f16(O[0][2*p+1], af[0], bb[2], bb[3]);
                mma_f16(O[1][2*p],   af[1], bb[0], bb[1]);
                mma_f16(O[1][2*p+1], af[1], bb[2], bb[3]);
            }
        }
        __syncthreads();
    }

    // ---- rowsum reduction ----
    #pragma unroll
    for (int mi = 0; mi < 2; mi++)
        #pragma unroll
        for (int j = 0; j < 2; j++) {
            rs[mi][j] += __shfl_xor_sync(0xffffffffu, rs[mi][j], 1);
            rs[mi][j] += __shfl_xor_sync(0xffffffffu, rs[mi][j], 2);
        }
    if (r == 0) {
        #pragma unroll
        for (int mi = 0; mi < 2; mi++)
            #pragma unroll
            for (int j = 0; j < 2; j++)
                l_part[wc][wr*32 + mi*16 + j*8 + q] = rs[mi][j];
    }
    __syncthreads();
    float inv[2][2];
    #pragma unroll
    for (int mi = 0; mi < 2; mi++)
        #pragma unroll
        for (int j = 0; j < 2; j++) {
            int row = wr*32 + mi*16 + j*8 + q;
            float l = l_part[0][row] + l_part[1][row];
            inv[mi][j] = 1.0f / l;
            if (wc == 0 && r == 0)
                g_l[(size_t)bh*SS + m0 + row] = l;
        }

    // ---- O cross-warp reduction + store ----
    float* scr = (float*)vs0;
    if (wc == 1) {
        #pragma unroll
        for (int mi = 0; mi < 2; mi++)
            #pragma unroll
            for (int nj = 0; nj < 8; nj++)
                #pragma unroll
                for (int p = 0; p < 4; p++) {
                    int idx = (mi*8 + nj)*4 + p;
                    scr[(wr*64 + idx)*32 + lane] = O[mi][nj][p];
                }
    }
    __syncthreads();
    if (wc == 0) {
        #pragma unroll
        for (int mi = 0; mi < 2; mi++)
            #pragma unroll
            for (int nj = 0; nj < 8; nj++) {
                #pragma unroll
                for (int p = 0; p < 4; p++) {
                    int idx = (mi*8 + nj)*4 + p;
                    O[mi][nj][p] += scr[(wr*64 + idx)*32 + lane];
                }
                int row = m0 + wr*32 + mi*16 + q;
                int col = h*64 + nj*8 + 2*r;
                *(uint32_t*)&g_atth[((size_t)(b*SS + row))*DD + col] =
                    pack_h2(O[mi][nj][0]*inv[mi][0], O[mi][nj][1]*inv[mi][0]);
                *(uint32_t*)&g_atth[((size_t)(b*SS + row + 8))*DD + col] =
                    pack_h2(O[mi][nj][2]*inv[mi][1], O[mi][nj][3]*inv[mi][1]);
            }
    }
}

// ============================================================================
// norm_w: w[row,:] = fp16_to_fp32(wh[row,:]) / l[row].  Pure memory.
// One block per row; 256 threads x 8 halves.
// ============================================================================
__global__ void __launch_bounds__(256) norm_w(float* __restrict__ w, int bh0) {
    size_t row = (size_t)bh0*SS + blockIdx.x;
    float scale = 1.0f / g_l[row];
    const uint4* src = (const uint4*)(g_wh + row*(size_t)SS);
    float4* dst = (float4*)(w + row*(size_t)SS);
    int t = threadIdx.x;
    uint4 v = __ldcs(&src[t]);
    __half2* hp = (__half2*)&v;
    float2 a = __half22float2(hp[0]);
    float2 bq = __half22float2(hp[1]);
    float2 c = __half22float2(hp[2]);
    float2 d = __half22float2(hp[3]);
    float4 o0 = make_float4(a.x*scale, a.y*scale, bq.x*scale, bq.y*scale);
    float4 o1 = make_float4(c.x*scale, c.y*scale, d.x*scale, d.y*scale);
    __stcs(&dst[t*2],     o0);
    __stcs(&dst[t*2 + 1], o1);
}

// ---------------- final: mix + LN-post ----------------
__global__ void final_kernel(const float* __restrict__ g, const float* __restrict__ b,
                             float* __restrict__ out) {
    __shared__ float red[256], red2[256];
    size_t row = blockIdx.x;
    int t = threadIdx.x;
    float gm = c_misc[1];
    float vals[4]; float s1 = 0.f, s2 = 0.f;
    #pragma unroll
    for (int l = 0; l < 4; l++) {
        size_t idx = row*DD + t + l*256;
        float vv = g_proj[idx]*gm + g_xn[idx]*(1.f - gm);
        vals[l] = vv; s1 += vv; s2 += vv*vv;
    }
    red[t] = s1; red2[t] = s2; __syncthreads();
    for (int off = 128; off > 0; off >>= 1) {
        if (t < off) { red[t] += red[t+off]; red2[t] += red2[t+off]; }
        __syncthreads();
    }
    float m = red[0]*(1.0f/DD);
    float var = red2[0]*(1.0f/DD) - m*m;
    float inv = rsqrtf(var + 1e-5f);
    #pragma unroll
    for (int l = 0; l < 4; l++) {
        int i = t + l*256;
        out[row*DD + i] = (vals[l]-m)*inv*g[i] + b[i];
    }
}

// ---------------------------------------------------------------------------
extern "C" void kernel_launch(void* const* d_in, const int* in_sizes, int n_in,
                              void* d_out, int out_size) {
    const float* x      = (const float*)d_in[0];
    const float* cf     = (const float*)d_in[1];
    const float* lnpg   = (const float*)d_in[2];
    const float* lnpb   = (const float*)d_in[3];
    const float* Wqkv   = (const float*)d_in[4];
    const float* bqkv   = (const float*)d_in[5];
    const float* eW1    = (const float*)d_in[6];
    const float* eb1    = (const float*)d_in[7];
    const float* eg1    = (const float*)d_in[8];
    const float* ebb1   = (const float*)d_in[9];
    const float* eW2    = (const float*)d_in[10];
    const float* eb2    = (const float*)d_in[11];
    const float* eg2    = (const float*)d_in[12];
    const float* ebb2   = (const float*)d_in[13];
    const float* Wga    = (const float*)d_in[14];
    const float* bga    = (const float*)d_in[15];
    const float* Wgv    = (const float*)d_in[16];
    const float* bgv    = (const float*)d_in[17];
    const float* Wt     = (const float*)d_in[18];
    const float* bt     = (const float*)d_in[19];
    const float* qrot   = (const float*)d_in[20];
    const float* fsc    = (const float*)d_in[21];
    const float* Wout   = (const float*)d_in[22];
    const float* bout   = (const float*)d_in[23];
    const float* lnqg   = (const float*)d_in[24];
    const float* lnqb   = (const float*)d_in[25];

    float* out = (float*)d_out;

    size_t need = (size_t)BS*DD + (size_t)BH*SS*SS;
    float* wbuf;
    if ((size_t)out_size >= need) {
        wbuf = out + (size_t)BS*DD;
    } else {
        float* wptr = nullptr;
        cudaGetSymbolAddress((void**)&wptr, g_w);
        wbuf = wptr;
    }

    __half *xnh_p, *qh_p, *kh_p, *vh_p, *atth_p, *wqkvh_p, *wouth_p;
    cudaGetSymbolAddress((void**)&xnh_p,   g_xnh);
    cudaGetSymbolAddress((void**)&qh_p,    g_qh);
    cudaGetSymbolAddress((void**)&kh_p,    g_kh);
    cudaGetSymbolAddress((void**)&vh_p,    g_vh);
    cudaGetSymbolAddress((void**)&atth_p,  g_atth);
    cudaGetSymbolAddress((void**)&wqkvh_p, g_wqkvh);
    cudaGetSymbolAddress((void**)&wouth_p, g_wouth);

    static cudaStream_t s2 = nullptr;
    static cudaEvent_t evA, evB, ev1, ev2, evD;
    if (!s2) {
        cudaStreamCreateWithFlags(&s2, cudaStreamNonBlocking);
        cudaEventCreateWithFlags(&evA, cudaEventDisableTiming);
        cudaEventCreateWithFlags(&evB, cudaEventDisableTiming);
        cudaEventCreateWithFlags(&ev1, cudaEventDisableTiming);
        cudaEventCreateWithFlags(&ev2, cudaEventDisableTiming);
        cudaEventCreateWithFlags(&evD, cudaEventDisableTiming);
        cudaFuncSetAttribute(attn_pass1,
                             cudaFuncAttributeMaxDynamicSharedMemorySize,
                             ATT_SMEM_BYTES);
        cudaFuncSetAttribute(gemm_f16<EpiQKV>,
                             cudaFuncAttributeMaxDynamicSharedMemorySize,
                             GE_SMEM_BYTES);
        cudaFuncSetAttribute(gemm_f16<EpiOut>,
                             cudaFuncAttributeMaxDynamicSharedMemorySize,
                             GE_SMEM_BYTES);
    }

    // ---- fork: chaos chain + weight rounding on s2, LN-pre on stream 0 ----
    cudaEventRecord(evA, 0);
    cudaStreamWaitEvent(s2, evA, 0);
    chaos1_kernel<<<1, 256, 0, s2>>>(cf, eW1, eb1, eg1, ebb1, Wga, bga, Wgv, bgv, Wt, bt);
    chaos2_kernel<<<64, 256, 0, s2>>>(eW2, eb2);
    chaos3_kernel<<<1, 256, 0, s2>>>(eg2, ebb2, qrot, fsc);
    round_weights<<<(3*DD*DD + DD*DD)/(256*4), 256, 0, s2>>>(Wqkv, Wout);
    cudaEventRecord(evB, s2);

    ln_pre_kernel<<<BS, 256>>>(x, lnpg, lnpb);
    cudaStreamWaitEvent(0, evB, 0);

    // QKV GEMM
    gemm_f16<EpiQKV><<<dim3(3*DD/128, BS/128), 256, GE_SMEM_BYTES>>>(
        xnh_p, wqkvh_p, EpiQKV{bqkv});

    // ---- attention halves; memory-bound normalize overlapped on s2 ----
    attn_pass1<<<dim3(SS/128, BH/2), 256, ATT_SMEM_BYTES>>>(qh_p, kh_p, vh_p, 0);
    cudaEventRecord(ev1, 0);
    cudaStreamWaitEvent(s2, ev1, 0);
    norm_w<<<(BH/2)*SS, 256, 0, s2>>>(wbuf, 0);        // overlaps pass1-B (tensor)

    attn_pass1<<<dim3(SS/128, BH/2), 256, ATT_SMEM_BYTES>>>(qh_p, kh_p, vh_p, BH/2);
    cudaEventRecord(ev2, 0);
    cudaStreamWaitEvent(s2, ev2, 0);
    norm_w<<<(BH/2)*SS, 256, 0, s2>>>(wbuf, BH/2);     // overlaps out-proj + final
    cudaEventRecord(evD, s2);

    gemm_f16<EpiOut><<<dim3(DD/128, BS/128), 256, GE_SMEM_BYTES>>>(
        atth_p, wouth_p, EpiOut{bout});
    final_kernel<<<BS, 256>>>(lnqg, lnqb, out);
    cudaStreamWaitEvent(0, evD, 0);
}

// round 9
// speedup vs baseline: 1.1675x; 1.1675x over previous
#include <cuda_runtime.h>
#include <cuda_fp16.h>
#include <math.h>
#include <stdint.h>

#define BB 2
#define SS 2048
#define DD 1024
#define HH 16
#define HD 64
#define CC 16
#define BS (BB*SS)
#define BH (BB*HH)

// ---------------- device scratch ----------------
__device__ __align__(256) float  g_xn[BS*DD];
__device__ __align__(256) __half g_xnh[BS*DD];
__device__ __align__(256) __half g_qh[BH*SS*HD];
__device__ __align__(256) __half g_kh[BH*SS*HD];
__device__ __align__(256) __half g_vh[BH*SS*HD];        // V row-major [bh][s][hd]
__device__ __align__(256) __half g_atth[BS*DD];
__device__ __align__(256) float  g_proj[BS*DD];
__device__ __align__(256) __half g_wqkvh[3*DD*DD];
__device__ __align__(256) __half g_wouth[DD*DD];
__device__ __align__(256) float  g_l[BH*SS];
__device__ __align__(256) float  g_w[(size_t)BH*SS*SS];

__device__ float c_h1[DD];
__device__ float c_cepre[DD];
__device__ float c_gate_a[HH];
__device__ float c_gate_v[HH];
__device__ float c_misc[2];
__device__ float c_alpha[HH];
__device__ float c_beta[HH];
__device__ float c_vadd[DD];

// ---------------- helpers ----------------
__device__ __forceinline__ uint32_t pack_h2(float a, float b) {
    __half2 h = __floats2half2_rn(a, b);
    return *reinterpret_cast<uint32_t*>(&h);
}

__device__ __forceinline__ float fast_exp2(float x) {
    float z = x + 12582912.0f;
    int   i = __float_as_int(z);
    float f = x - (z - 12582912.0f);
    float p = 9.618129e-3f;
    p = fmaf(p, f, 5.5504109e-2f);
    p = fmaf(p, f, 2.4022651e-1f);
    p = fmaf(p, f, 6.9314718e-1f);
    p = fmaf(p, f, 1.0f);
    return __int_as_float(__float_as_int(p) + (i << 23));
}

__device__ __forceinline__ void mma_f16(float c[4], const uint32_t a[4],
                                        uint32_t b0, uint32_t b1) {
    asm volatile(
        "mma.sync.aligned.m16n8k16.row.col.f32.f16.f16.f32 "
        "{%0,%1,%2,%3}, {%4,%5,%6,%7}, {%8,%9}, {%0,%1,%2,%3};"
        : "+f"(c[0]), "+f"(c[1]), "+f"(c[2]), "+f"(c[3])
        : "r"(a[0]), "r"(a[1]), "r"(a[2]), "r"(a[3]), "r"(b0), "r"(b1));
}

__device__ __forceinline__ uint32_t lds_addr(const void* p) {
    return (uint32_t)__cvta_generic_to_shared(p);
}
__device__ __forceinline__ void ldsm4(uint32_t r[4], uint32_t a) {
    asm volatile("ldmatrix.sync.aligned.m8n8.x4.shared.b16 {%0,%1,%2,%3}, [%4];"
                 : "=r"(r[0]), "=r"(r[1]), "=r"(r[2]), "=r"(r[3]) : "r"(a));
}
__device__ __forceinline__ void ldsm4t(uint32_t r[4], uint32_t a) {
    asm volatile("ldmatrix.sync.aligned.m8n8.x4.trans.shared.b16 {%0,%1,%2,%3}, [%4];"
                 : "=r"(r[0]), "=r"(r[1]), "=r"(r[2]), "=r"(r[3]) : "r"(a));
}

__device__ __forceinline__ void cp16h(__half* dst, const __half* src) {
    unsigned d = (unsigned)__cvta_generic_to_shared(dst);
    asm volatile("cp.async.cg.shared.global [%0], [%1], 16;" :: "r"(d), "l"(src));
}
__device__ __forceinline__ void cp_commit() { asm volatile("cp.async.commit_group;"); }
__device__ __forceinline__ void cp_wait1() { asm volatile("cp.async.wait_group 1;"); }
__device__ __forceinline__ void cp_wait0() { asm volatile("cp.async.wait_group 0;"); }

// ---------------- chaos encoder ----------------
__global__ void chaos1_kernel(const float* __restrict__ cf,
                              const float* __restrict__ W1, const float* __restrict__ b1,
                              const float* __restrict__ g1, const float* __restrict__ bb1,
                              const float* __restrict__ Wga, const float* __restrict__ bga,
                              const float* __restrict__ Wgv, const float* __restrict__ bgv,
                              const float* __restrict__ Wt,  const float* __restrict__ bt) {
    __shared__ float cfs[CC];
    __shared__ float red[256], red2[256];
    int t = threadIdx.x;
    if (t < CC) cfs[t] = cf[t];
    __syncthreads();

    if (t < HH) {
        float sa = bga[t], sv = bgv[t];
        #pragma unroll
        for (int c = 0; c < CC; c++) { sa += cfs[c]*Wga[t*CC+c]; sv += cfs[c]*Wgv[t*CC+c]; }
        c_gate_a[t] = 1.f/(1.f+expf(-sa));
        c_gate_v[t] = 1.f/(1.f+expf(-sv));
    } else if (t == 16) {
        float s = bt[0];
        #pragma unroll
        for (int c = 0; c < CC; c++) s += cfs[c]*Wt[c];
        float sp = (s > 20.f) ? s : log1pf(expf(s));
        c_misc[0] = sp + 1.0f;
    } else if (t == 17) {
        float s = 0.f;
        #pragma unroll
        for (int c = 0; c < CC; c++) s += cfs[c];
        s *= (1.0f/CC);
        c_misc[1] = (1.f/(1.f+expf(-s)))*0.5f + 0.5f;
    }

    float vals[4];
    float s1 = 0.f, s2 = 0.f;
    #pragma unroll
    for (int l = 0; l < 4; l++) {
        int i = t*4 + l;
        float a = b1[i];
        #pragma unroll
        for (int c = 0; c < CC; c++) a += cfs[c]*W1[i*CC+c];
        vals[l] = a; s1 += a; s2 += a*a;
    }
    red[t] = s1; red2[t] = s2; __syncthreads();
    for (int o = 128; o > 0; o >>= 1) {
        if (t < o) { red[t] += red[t+o]; red2[t] += red2[t+o]; }
        __syncthreads();
    }
    float m = red[0]*(1.0f/DD);
    float var = red2[0]*(1.0f/DD) - m*m;
    float inv = rsqrtf(var + 1e-5f);
    #pragma unroll
    for (int l = 0; l < 4; l++) {
        int i = t*4 + l;
        float h = (vals[l]-m)*inv*g1[i] + bb1[i];
        c_h1[i] = fmaxf(h, 0.f);
    }
}

__global__ void chaos2_kernel(const float* __restrict__ W2, const float* __restrict__ b2) {
    __shared__ float h1s[DD];
    __shared__ float red[256];
    int t = threadIdx.x;
    #pragma unroll
    for (int l = 0; l < 4; l++) h1s[t + l*256] = c_h1[t + l*256];
    __syncthreads();
    int r = t >> 4, c = t & 15;
    int i = blockIdx.x*16 + r;
    float s = 0.f;
    for (int j = c; j < DD; j += 16) s += h1s[j]*W2[(size_t)i*DD + j];
    red[t] = s; __syncthreads();
    for (int o = 8; o > 0; o >>= 1) {
        if (c < o) red[t] += red[t+o];
        __syncthreads();
    }
    if (c == 0) c_cepre[i] = red[r*16] + b2[i];
}

__global__ void chaos3_kernel(const float* __restrict__ g2, const float* __restrict__ bb2,
                              const float* __restrict__ qrot, const float* __restrict__ fscales) {
    __shared__ float ce[DD];
    __shared__ float scs[DD];
    __shared__ float red[256], red2[256];
    int t = threadIdx.x;
    float vals[4]; float s1 = 0.f, s2 = 0.f;
    #pragma unroll
    for (int l = 0; l < 4; l++) {
        int i = t + l*256;
        vals[l] = c_cepre[i]; s1 += vals[l]; s2 += vals[l]*vals[l];
    }
    red[t] = s1; red2[t] = s2; __syncthreads();
    for (int o = 128; o > 0; o >>= 1) {
        if (t < o) { red[t] += red[t+o]; red2[t] += red2[t+o]; }
        __syncthreads();
    }
    float m = red[0]*(1.0f/DD);
    float var = red2[0]*(1.0f/DD) - m*m;
    float inv = rsqrtf(var + 1e-5f);
    #pragma unroll
    for (int l = 0; l < 4; l++) {
        int i = t + l*256;
        ce[i] = (vals[l]-m)*inv*g2[i] + bb2[i];
    }
    __syncthreads();
    float sfs = 1.f/(1.f+expf(-fscales[0]));
    #pragma unroll
    for (int l = 0; l < 4; l++) {
        int i = t + l*256;
        int h = i >> 6, d = i & 63;
        float s = 0.f;
        #pragma unroll 8
        for (int e = 0; e < HD; e++) s += ce[h*HD+e]*qrot[e*HD+d];
        s *= sfs;
        scs[i] = s;
        c_vadd[i] = s * c_gate_v[h];
    }
    __syncthreads();
    if (t < HH) {
        float bsum = 0.f;
        for (int d = 0; d < HD; d++) bsum += scs[t*HD + d];
        float temp = c_misc[0];
        c_alpha[t] = c_gate_a[t]/(8.f*temp);
        c_beta[t]  = bsum/temp;
    }
}

// ---------------- LN-pre ----------------
__global__ void ln_pre_kernel(const float* __restrict__ x,
                              const float* __restrict__ g, const float* __restrict__ b) {
    __shared__ float red[256], red2[256];
    size_t row = blockIdx.x;
    const float4* xr = (const float4*)(x + row*DD);
    int t = threadIdx.x;
    float4 v = xr[t];
    float s1 = v.x + v.y + v.z + v.w;
    float s2 = v.x*v.x + v.y*v.y + v.z*v.z + v.w*v.w;
    red[t] = s1; red2[t] = s2; __syncthreads();
    for (int off = 128; off > 0; off >>= 1) {
        if (t < off) { red[t] += red[t+off]; red2[t] += red2[t+off]; }
        __syncthreads();
    }
    float m = red[0]*(1.0f/DD);
    float var = red2[0]*(1.0f/DD) - m*m;
    float inv = rsqrtf(var + 1e-5f);
    int i = t*4;
    float4 gg = *(const float4*)(g + i);
    float4 bb = *(const float4*)(b + i);
    float4 o;
    o.x = (v.x-m)*inv*gg.x + bb.x;
    o.y = (v.y-m)*inv*gg.y + bb.y;
    o.z = (v.z-m)*inv*gg.z + bb.z;
    o.w = (v.w-m)*inv*gg.w + bb.w;
    *(float4*)(g_xn + row*DD + i) = o;
    uint2 h;
    h.x = pack_h2(o.x, o.y);
    h.y = pack_h2(o.z, o.w);
    *(uint2*)(g_xnh + row*DD + i) = h;
}

// ---------------- convert weights to half ----------------
__global__ void round_weights(const float* __restrict__ Wqkv,
                              const float* __restrict__ Wout) {
    size_t i = (size_t)blockIdx.x*256 + threadIdx.x;
    const size_t nqkv = (size_t)3*DD*DD/4;
    float4 v;
    __half* dst;
    if (i < nqkv) {
        v = ((const float4*)Wqkv)[i];
        dst = g_wqkvh + i*4;
    } else {
        v = ((const float4*)Wout)[i - nqkv];
        dst = g_wouth + (i - nqkv)*4;
    }
    uint2 h;
    h.x = pack_h2(v.x, v.y);
    h.y = pack_h2(v.z, v.w);
    *(uint2*)dst = h;
}

// ============================================================================
// fp16 tensor-core GEMM (NT) with ldmatrix fragment loads.  2 CTAs/SM.
// ============================================================================
#define GE_BK 64
#define GE_STR 72
#define GE_TILE_H (128*GE_STR)
#define GE_SMEM_BYTES (4*GE_TILE_H*2)

struct EpiQKV {
    const float* bias;
    __device__ __forceinline__ void write2(int m, int n, float v0, float v1) const {
        v0 += bias[n]; v1 += bias[n+1];
        int b = m >> 11, s = m & 2047;
        int which = n >> 10, rest = n & 1023;
        int h = rest >> 6, dd = rest & 63;
        int bh = b*HH + h;
        size_t dst = ((size_t)bh*SS + s)*HD + dd;
        if (which == 0) {
            *(uint32_t*)&g_qh[dst] = pack_h2(v0, v1);
        } else if (which == 1) {
            *(uint32_t*)&g_kh[dst] = pack_h2(v0, v1);
        } else {
            v0 += c_vadd[rest]; v1 += c_vadd[rest+1];
            *(uint32_t*)&g_vh[dst] = pack_h2(v0, v1);
        }
    }
};

struct EpiOut {
    const float* bias;
    __device__ __forceinline__ void write2(int m, int n, float v0, float v1) const {
        float2 o = make_float2(v0 + bias[n], v1 + bias[n+1]);
        *(float2*)&g_proj[(size_t)m*DD + n] = o;
    }
};

__device__ __forceinline__ void ge_load(__half* dstA, __half* dstB,
                                        const __half* A, const __half* B,
                                        int m0, int n0, int k0, int t) {
    #pragma unroll
    for (int i = 0; i < 4; i++) {
        int f = t + i*256;
        int row = f >> 3, c = f & 7;
        cp16h(dstA + row*GE_STR + c*8, A + (size_t)(m0+row)*DD + k0 + c*8);
    }
    #pragma unroll
    for (int i = 0; i < 4; i++) {
        int f = t + i*256;
        int row = f >> 3, c = f & 7;
        cp16h(dstB + row*GE_STR + c*8, B + (size_t)(n0+row)*DD + k0 + c*8);
    }
}

template<typename Epi>
__global__ void __launch_bounds__(256, 2) gemm_f16(
    const __half* __restrict__ A, const __half* __restrict__ B, Epi epi)
{
    extern __shared__ __half gsm[];
    __half* As[2] = { gsm,                gsm + 2*GE_TILE_H };
    __half* Bs[2] = { gsm + GE_TILE_H,    gsm + 3*GE_TILE_H };

    int t = threadIdx.x, lane = t & 31, warp = t >> 5;
    int q = lane >> 2, r = lane & 3;
    int wm = (warp >> 1) * 32;
    int wn = (warp & 1) * 64;
    int m0 = blockIdx.y * 128, n0 = blockIdx.x * 128;

    int a_off = (wm + (lane & 15))*GE_STR + (lane >> 4)*8;
    int b_off = (wn + (lane & 7) + ((lane & 16) >> 1))*GE_STR + (lane & 8);

    float acc[2][8][4] = {};

    ge_load(As[0], Bs[0], A, B, m0, n0, 0, t);
    cp_commit();

    for (int kt = 0; kt < DD/GE_BK; kt++) {
        int cur = kt & 1;
        if (kt + 1 < DD/GE_BK) {
            ge_load(As[cur^1], Bs[cur^1], A, B, m0, n0, (kt+1)*GE_BK, t);
            cp_commit();
            cp_wait1();
        } else {
            cp_wait0();
        }
        __syncthreads();

        uint32_t asb = lds_addr(As[cur]);
        uint32_t bsb = lds_addr(Bs[cur]);
        #pragma unroll
        for (int ks = 0; ks < 4; ks++) {
            uint32_t af[2][4];
            ldsm4(af[0], asb + 2*(a_off + ks*16));
            ldsm4(af[1], asb + 2*(a_off + 16*GE_STR + ks*16));
            #pragma unroll
            for (int p = 0; p < 4; p++) {
                uint32_t bb[4];
                ldsm4(bb, bsb + 2*(b_off + p*16*GE_STR + ks*16));
                mma_f16(acc[0][2*p],   af[0], bb[0], bb[1]);
                mma_f16(acc[0][2*p+1], af[0], bb[2], bb[3]);
                mma_f16(acc[1][2*p],   af[1], bb[0], bb[1]);
                mma_f16(acc[1][2*p+1], af[1], bb[2], bb[3]);
            }
        }
        __syncthreads();
    }

    #pragma unroll
    for (int mi = 0; mi < 2; mi++)
        #pragma unroll
        for (int nj = 0; nj < 8; nj++) {
            int m = m0 + wm + mi*16 + q;
            int n = n0 + wn + nj*8 + 2*r;
            epi.write2(m,     n, acc[mi][nj][0], acc[mi][nj][1]);
            epi.write2(m + 8, n, acc[mi][nj][2], acc[mi][nj][3]);
        }
}

// ============================================================================
// Attention pass 1 (bh-half): S=QK^T -> exp2 -> rowsum + O += P@V.
// ============================================================================
#define QS_STR 72
#define Q_HALVES (128*QS_STR)
#define ATT_SMEM_BYTES (5*Q_HALVES*2)   // Q,K0,K1,V0,V1 = 92160
#define P2_SMEM_BYTES (3*Q_HALVES*2)    // Q,K0,K1 = 55296

__device__ __forceinline__ void att_load_k(__half* dst, const __half* src, int t) {
    #pragma unroll
    for (int i = 0; i < 4; i++) {
        int f = t + i*256;
        int row = f >> 3, c = f & 7;
        cp16h(dst + row*QS_STR + c*8, src + (size_t)row*HD + c*8);
    }
}

__global__ void __launch_bounds__(256, 1) attn_pass1(
    const __half* __restrict__ qg, const __half* __restrict__ kg,
    const __half* __restrict__ vg, int bh0)
{
    extern __shared__ __half asm_[];
    __half* qs  = asm_;
    __half* ks0 = asm_ + Q_HALVES;
    __half* ks1 = asm_ + 2*Q_HALVES;
    __half* vs0 = asm_ + 3*Q_HALVES;
    __half* vs1 = asm_ + 4*Q_HALVES;
    __shared__ float l_part[2][128];

    int t = threadIdx.x, lane = t & 31, warp = t >> 5;
    int q = lane >> 2, r = lane & 3;
    int wr = warp >> 1, wc = warp & 1;
    int m0 = blockIdx.x*128, bh = bh0 + blockIdx.y;
    int h = bh & 15, b = bh >> 4;
    const __half* Q = qg + ((size_t)bh*SS + m0)*HD;
    const __half* K = kg + (size_t)bh*SS*HD;
    const __half* V = vg + (size_t)bh*SS*HD;
    const float LOG2E = 1.4426950408889634f;
    float al2 = c_alpha[h]*LOG2E, be2 = c_beta[h]*LOG2E;

    #pragma unroll
    for (int i = 0; i < 4; i++) {
        int f = t + i*256;
        int row = f >> 3, c = f & 7;
        *(uint4*)&qs[row*QS_STR + c*8] = *(const uint4*)(Q + (size_t)row*HD + c*8);
    }

    att_load_k(ks0, K, t);
    att_load_k(vs0, V, t);
    cp_commit();
    __syncthreads();

    uint32_t qf[2][4][4];
    {
        uint32_t qsb = lds_addr(qs);
        int q_off = (wr*32 + (lane & 15))*QS_STR + (lane >> 4)*8;
        #pragma unroll
        for (int mi = 0; mi < 2; mi++)
            #pragma unroll
            for (int ks = 0; ks < 4; ks++)
                ldsm4(qf[mi][ks], qsb + 2*(q_off + mi*16*QS_STR + ks*16));
    }

    int k_off = (wc*64 + (lane & 7) + ((lane & 16) >> 1))*QS_STR + (lane & 8);
    int v_off = (wc*64 + (lane & 15))*QS_STR + (lane >> 4)*8;

    float O[2][8][4] = {};
    float rs[2][2] = {};

    for (int kt = 0; kt < 16; kt++) {
        __half* kss = (kt & 1) ? ks1 : ks0;
        __half* vss = (kt & 1) ? vs1 : vs0;
        if (kt < 15) {
            att_load_k((kt & 1) ? ks0 : ks1, K + (size_t)(kt+1)*128*HD, t);
            att_load_k((kt & 1) ? vs0 : vs1, V + (size_t)(kt+1)*128*HD, t);
            cp_commit();
            cp_wait1();
        } else {
            cp_wait0();
        }
        __syncthreads();

        // ---- S = Q K^T ----
        float acc[2][8][4] = {};
        uint32_t ksb = lds_addr(kss);
        #pragma unroll
        for (int ks = 0; ks < 4; ks++) {
            #pragma unroll
            for (int p = 0; p < 4; p++) {
                uint32_t bb[4];
                ldsm4(bb, ksb + 2*(k_off + p*16*QS_STR + ks*16));
                mma_f16(acc[0][2*p],   qf[0][ks], bb[0], bb[1]);
                mma_f16(acc[0][2*p+1], qf[0][ks], bb[2], bb[3]);
                mma_f16(acc[1][2*p],   qf[1][ks], bb[0], bb[1]);
                mma_f16(acc[1][2*p+1], qf[1][ks], bb[2], bb[3]);
            }
        }
        // ---- exp + rowsum ----
        #pragma unroll
        for (int mi = 0; mi < 2; mi++)
            #pragma unroll
            for (int nj = 0; nj < 8; nj++) {
                float e0 = fast_exp2(fmaf(al2, acc[mi][nj][0], be2));
                float e1 = fast_exp2(fmaf(al2, acc[mi][nj][1], be2));
                float e2 = fast_exp2(fmaf(al2, acc[mi][nj][2], be2));
                float e3 = fast_exp2(fmaf(al2, acc[mi][nj][3], be2));
                acc[mi][nj][0] = e0; acc[mi][nj][1] = e1;
                acc[mi][nj][2] = e2; acc[mi][nj][3] = e3;
                rs[mi][0] += e0 + e1;
                rs[mi][1] += e2 + e3;
            }
        // ---- O += P @ V ----
        uint32_t vsb = lds_addr(vss);
        #pragma unroll
        for (int kk = 0; kk < 4; kk++) {
            uint32_t af[2][4];
            #pragma unroll
            for (int mi = 0; mi < 2; mi++) {
                af[mi][0] = pack_h2(acc[mi][2*kk][0],   acc[mi][2*kk][1]);
                af[mi][1] = pack_h2(acc[mi][2*kk][2],   acc[mi][2*kk][3]);
                af[mi][2] = pack_h2(acc[mi][2*kk+1][0], acc[mi][2*kk+1][1]);
                af[mi][3] = pack_h2(acc[mi][2*kk+1][2], acc[mi][2*kk+1][3]);
            }
            #pragma unroll
            for (int p = 0; p < 4; p++) {
                uint32_t bb[4];
                ldsm4t(bb, vsb + 2*(v_off + kk*16*QS_STR + p*16));
                mma_f16(O[0][2*p],   af[0], bb[0], bb[1]);
                mma_f16(O[0][2*p+1], af[0], bb[2], bb[3]);
                mma_f16(O[1][2*p],   af[1], bb[0], bb[1]);
                mma_f16(O[1][2*p+1], af[1], bb[2], bb[3]);
            }
        }
        __syncthreads();
    }

    // ---- rowsum reduction ----
    #pragma unroll
    for (int mi = 0; mi < 2; mi++)
        #pragma unroll
        for (int j = 0; j < 2; j++) {
            rs[mi][j] += __shfl_xor_sync(0xffffffffu, rs[mi][j], 1);
            rs[mi][j] += __shfl_xor_sync(0xffffffffu, rs[mi][j], 2);
        }
    if (r == 0) {
        #pragma unroll
        for (int mi = 0; mi < 2; mi++)
            #pragma unroll
            for (int j = 0; j < 2; j++)
                l_part[wc][wr*32 + mi*16 + j*8 + q] = rs[mi][j];
    }
    __syncthreads();
    float inv[2][2];
    #pragma unroll
    for (int mi = 0; mi < 2; mi++)
        #pragma unroll
        for (int j = 0; j < 2; j++) {
            int row = wr*32 + mi*16 + j*8 + q;
            float l = l_part[0][row] + l_part[1][row];
            inv[mi][j] = 1.0f / l;
            if (wc == 0 && r == 0)
                g_l[(size_t)bh*SS + m0 + row] = l;
        }

    // ---- O cross-warp reduction + store ----
    float* scr = (float*)vs0;
    if (wc == 1) {
        #pragma unroll
        for (int mi = 0; mi < 2; mi++)
            #pragma unroll
            for (int nj = 0; nj < 8; nj++)
                #pragma unroll
                for (int p = 0; p < 4; p++) {
                    int idx = (mi*8 + nj)*4 + p;
                    scr[(wr*64 + idx)*32 + lane] = O[mi][nj][p];
                }
    }
    __syncthreads();
    if (wc == 0) {
        #pragma unroll
        for (int mi = 0; mi < 2; mi++)
            #pragma unroll
            for (int nj = 0; nj < 8; nj++) {
                #pragma unroll
                for (int p = 0; p < 4; p++) {
                    int idx = (mi*8 + nj)*4 + p;
                    O[mi][nj][p] += scr[(wr*64 + idx)*32 + lane];
                }
                int row = m0 + wr*32 + mi*16 + q;
                int col = h*64 + nj*8 + 2*r;
                *(uint32_t*)&g_atth[((size_t)(b*SS + row))*DD + col] =
                    pack_h2(O[mi][nj][0]*inv[mi][0], O[mi][nj][1]*inv[mi][0]);
                *(uint32_t*)&g_atth[((size_t)(b*SS + row + 8))*DD + col] =
                    pack_h2(O[mi][nj][2]*inv[mi][1], O[mi][nj][3]*inv[mi][1]);
            }
    }
}

// ============================================================================
// Attention pass 2 (bh-half): recompute S, write w.  2 CTAs/SM (low regs:
// p-outer loop keeps only 16 live accumulators).
// ============================================================================
__global__ void __launch_bounds__(256, 2) attn_pass2(
    const __half* __restrict__ qg, const __half* __restrict__ kg,
    float* __restrict__ wout, int bh0)
{
    extern __shared__ __half asm2_[];
    __half* qs  = asm2_;
    __half* ks0 = asm2_ + Q_HALVES;
    __half* ks1 = asm2_ + 2*Q_HALVES;

    int t = threadIdx.x, lane = t & 31, warp = t >> 5;
    int q = lane >> 2, r = lane & 3;
    int wr = warp >> 1, wc = warp & 1;
    int m0 = blockIdx.x*128, bh = bh0 + blockIdx.y;
    int h = bh & 15;
    const __half* Q = qg + ((size_t)bh*SS + m0)*HD;
    const __half* K = kg + (size_t)bh*SS*HD;
    const float LOG2E = 1.4426950408889634f;
    float al2 = c_alpha[h]*LOG2E, be2 = c_beta[h]*LOG2E;

    #pragma unroll
    for (int i = 0; i < 4; i++) {
        int f = t + i*256;
        int row = f >> 3, c = f & 7;
        *(uint4*)&qs[row*QS_STR + c*8] = *(const uint4*)(Q + (size_t)row*HD + c*8);
    }
    att_load_k(ks0, K, t);
    cp_commit();

    float cc[2][2];
    #pragma unroll
    for (int mi = 0; mi < 2; mi++)
        #pragma unroll
        for (int j = 0; j < 2; j++) {
            int row = wr*32 + mi*16 + j*8 + q;
            cc[mi][j] = be2 - __log2f(g_l[(size_t)bh*SS + m0 + row]);
        }
    __syncthreads();

    uint32_t qf[2][4][4];
    {
        uint32_t qsb = lds_addr(qs);
        int q_off = (wr*32 + (lane & 15))*QS_STR + (lane >> 4)*8;
        #pragma unroll
        for (int mi = 0; mi < 2; mi++)
            #pragma unroll
            for (int ks = 0; ks < 4; ks++)
                ldsm4(qf[mi][ks], qsb + 2*(q_off + mi*16*QS_STR + ks*16));
    }
    int k_off = (wc*64 + (lane & 7) + ((lane & 16) >> 1))*QS_STR + (lane & 8);

    float* wbh = wout + (size_t)bh*SS*SS;
    for (int kt = 0; kt < 16; kt++) {
        __half* kss = (kt & 1) ? ks1 : ks0;
        if (kt < 15) {
            att_load_k((kt & 1) ? ks0 : ks1, K + (size_t)(kt+1)*128*HD, t);
            cp_commit();
            cp_wait1();
        } else {
            cp_wait0();
        }
        __syncthreads();

        uint32_t ksb = lds_addr(kss);
        // p-outer: only 16 live accumulators; stores interleave with mma
        #pragma unroll
        for (int p = 0; p < 4; p++) {
            float acc[2][2][4] = {};
            #pragma unroll
            for (int ks = 0; ks < 4; ks++) {
                uint32_t bb[4];
                ldsm4(bb, ksb + 2*(k_off + p*16*QS_STR + ks*16));
                mma_f16(acc[0][0], qf[0][ks], bb[0], bb[1]);
                mma_f16(acc[0][1], qf[0][ks], bb[2], bb[3]);
                mma_f16(acc[1][0], qf[1][ks], bb[0], bb[1]);
                mma_f16(acc[1][1], qf[1][ks], bb[2], bb[3]);
            }
            #pragma unroll
            for (int mi = 0; mi < 2; mi++) {
                int row = m0 + wr*32 + mi*16 + q;
                #pragma unroll
                for (int jj = 0; jj < 2; jj++) {
                    int col = kt*128 + wc*64 + (2*p + jj)*8 + 2*r;
                    float e0 = fast_exp2(fmaf(al2, acc[mi][jj][0], cc[mi][0]));
                    float e1 = fast_exp2(fmaf(al2, acc[mi][jj][1], cc[mi][0]));
                    float e2 = fast_exp2(fmaf(al2, acc[mi][jj][2], cc[mi][1]));
                    float e3 = fast_exp2(fmaf(al2, acc[mi][jj][3], cc[mi][1]));
                    __stcs((float2*)&wbh[(size_t)row*SS + col], make_float2(e0, e1));
                    __stcs((float2*)&wbh[(size_t)(row+8)*SS + col], make_float2(e2, e3));
                }
            }
        }
        __syncthreads();
    }
}

// ---------------- final: mix + LN-post ----------------
__global__ void final_kernel(const float* __restrict__ g, const float* __restrict__ b,
                             float* __restrict__ out) {
    __shared__ float red[256], red2[256];
    size_t row = blockIdx.x;
    int t = threadIdx.x;
    float gm = c_misc[1];
    float vals[4]; float s1 = 0.f, s2 = 0.f;
    #pragma unroll
    for (int l = 0; l < 4; l++) {
        size_t idx = row*DD + t + l*256;
        float vv = g_proj[idx]*gm + g_xn[idx]*(1.f - gm);
        vals[l] = vv; s1 += vv; s2 += vv*vv;
    }
    red[t] = s1; red2[t] = s2; __syncthreads();
    for (int off = 128; off > 0; off >>= 1) {
        if (t < off) { red[t] += red[t+off]; red2[t] += red2[t+off]; }
        __syncthreads();
    }
    float m = red[0]*(1.0f/DD);
    float var = red2[0]*(1.0f/DD) - m*m;
    float inv = rsqrtf(var + 1e-5f);
    #pragma unroll
    for (int l = 0; l < 4; l++) {
        int i = t + l*256;
        out[row*DD + i] = (vals[l]-m)*inv*g[i] + b[i];
    }
}

// ---------------------------------------------------------------------------
extern "C" void kernel_launch(void* const* d_in, const int* in_sizes, int n_in,
                              void* d_out, int out_size) {
    const float* x      = (const float*)d_in[0];
    const float* cf     = (const float*)d_in[1];
    const float* lnpg   = (const float*)d_in[2];
    const float* lnpb   = (const float*)d_in[3];
    const float* Wqkv   = (const float*)d_in[4];
    const float* bqkv   = (const float*)d_in[5];
    const float* eW1    = (const float*)d_in[6];
    const float* eb1    = (const float*)d_in[7];
    const float* eg1    = (const float*)d_in[8];
    const float* ebb1   = (const float*)d_in[9];
    const float* eW2    = (const float*)d_in[10];
    const float* eb2    = (const float*)d_in[11];
    const float* eg2    = (const float*)d_in[12];
    const float* ebb2   = (const float*)d_in[13];
    const float* Wga    = (const float*)d_in[14];
    const float* bga    = (const float*)d_in[15];
    const float* Wgv    = (const float*)d_in[16];
    const float* bgv    = (const float*)d_in[17];
    const float* Wt     = (const float*)d_in[18];
    const float* bt     = (const float*)d_in[19];
    const float* qrot   = (const float*)d_in[20];
    const float* fsc    = (const float*)d_in[21];
    const float* Wout   = (const float*)d_in[22];
    const float* bout   = (const float*)d_in[23];
    const float* lnqg   = (const float*)d_in[24];
    const float* lnqb   = (const float*)d_in[25];

    float* out = (float*)d_out;

    size_t need = (size_t)BS*DD + (size_t)BH*SS*SS;
    float* wbuf;
    if ((size_t)out_size >= need) {
        wbuf = out + (size_t)BS*DD;
    } else {
        float* wptr = nullptr;
        cudaGetSymbolAddress((void**)&wptr, g_w);
        wbuf = wptr;
    }

    __half *xnh_p, *qh_p, *kh_p, *vh_p, *atth_p, *wqkvh_p, *wouth_p;
    cudaGetSymbolAddress((void**)&xnh_p,   g_xnh);
    cudaGetSymbolAddress((void**)&qh_p,    g_qh);
    cudaGetSymbolAddress((void**)&kh_p,    g_kh);
    cudaGetSymbolAddress((void**)&vh_p,    g_vh);
    cudaGetSymbolAddress((void**)&atth_p,  g_atth);
    cudaGetSymbolAddress((void**)&wqkvh_p, g_wqkvh);
    cudaGetSymbolAddress((void**)&wouth_p, g_wouth);

    static cudaStream_t s2 = nullptr;
    static cudaEvent_t evA, evB, ev1, ev2, evD;
    if (!s2) {
        cudaStreamCreateWithFlags(&s2, cudaStreamNonBlocking);
        cudaEventCreateWithFlags(&evA, cudaEventDisableTiming);
        cudaEventCreateWithFlags(&evB, cudaEventDisableTiming);
        cudaEventCreateWithFlags(&ev1, cudaEventDisableTiming);
        cudaEventCreateWithFlags(&ev2, cudaEventDisableTiming);
        cudaEventCreateWithFlags(&evD, cudaEventDisableTiming);
        cudaFuncSetAttribute(attn_pass1,
                             cudaFuncAttributeMaxDynamicSharedMemorySize,
                             ATT_SMEM_BYTES);
        cudaFuncSetAttribute(attn_pass2,
                             cudaFuncAttributeMaxDynamicSharedMemorySize,
                             P2_SMEM_BYTES);
        cudaFuncSetAttribute(gemm_f16<EpiQKV>,
                             cudaFuncAttributeMaxDynamicSharedMemorySize,
                             GE_SMEM_BYTES);
        cudaFuncSetAttribute(gemm_f16<EpiOut>,
                             cudaFuncAttributeMaxDynamicSharedMemorySize,
                             GE_SMEM_BYTES);
    }

    // ---- fork: chaos chain + weight rounding on s2, LN-pre on stream 0 ----
    cudaEventRecord(evA, 0);
    cudaStreamWaitEvent(s2, evA, 0);
    chaos1_kernel<<<1, 256, 0, s2>>>(cf, eW1, eb1, eg1, ebb1, Wga, bga, Wgv, bgv, Wt, bt);
    chaos2_kernel<<<64, 256, 0, s2>>>(eW2, eb2);
    chaos3_kernel<<<1, 256, 0, s2>>>(eg2, ebb2, qrot, fsc);
    round_weights<<<(3*DD*DD + DD*DD)/(256*4), 256, 0, s2>>>(Wqkv, Wout);
    cudaEventRecord(evB, s2);

    ln_pre_kernel<<<BS, 256>>>(x, lnpg, lnpb);
    cudaStreamWaitEvent(0, evB, 0);

    // QKV GEMM
    gemm_f16<EpiQKV><<<dim3(3*DD/128, BS/128), 256, GE_SMEM_BYTES>>>(
        xnh_p, wqkvh_p, EpiQKV{bqkv});

    // ---- pipelined attention: pass1 halves; pass2 overlapped on s2 ----
    attn_pass1<<<dim3(SS/128, BH/2), 256, ATT_SMEM_BYTES>>>(qh_p, kh_p, vh_p, 0);
    cudaEventRecord(ev1, 0);
    cudaStreamWaitEvent(s2, ev1, 0);
    attn_pass2<<<dim3(SS/128, BH/2), 256, P2_SMEM_BYTES, s2>>>(qh_p, kh_p, wbuf, 0);

    attn_pass1<<<dim3(SS/128, BH/2), 256, ATT_SMEM_BYTES>>>(qh_p, kh_p, vh_p, BH/2);
    cudaEventRecord(ev2, 0);
    cudaStreamWaitEvent(s2, ev2, 0);
    attn_pass2<<<dim3(SS/128, BH/2), 256, P2_SMEM_BYTES, s2>>>(qh_p, kh_p, wbuf, BH/2);
    cudaEventRecord(evD, s2);

    // out projection + final on stream 0 (overlap with pass2-B)
    gemm_f16<EpiOut><<<dim3(DD/128, BS/128), 256, GE_SMEM_BYTES>>>(
        atth_p, wouth_p, EpiOut{bout});
    final_kernel<<<BS, 256>>>(lnqg, lnqb, out);
    cudaStreamWaitEvent(0, evD, 0);
}